// round 7
// baseline (speedup 1.0000x reference)
#include <cuda_runtime.h>
#include <cuda_fp16.h>
#include <cstdint>

#define OUTF 2048
#define INF  2048
#define NNZV 262144
#define NN   65536

#define TM 128        // output tile
#define TN 128        // node tile
#define TKO 128       // ORIGINAL k per iteration (compressed: 64 halves)
#define NKSTEPS (INF / TKO)   // 16

#define ROWH_A 72     // A smem row stride in halves (144 B; data 128 B = 64 ck)
#define ROWH_B 136    // B smem row stride in halves (272 B; data 256 B = 128 k)
#define A_STAGE_B (TM * ROWH_A * 2)   // 18432
#define B_STAGE_B (TN * ROWH_B * 2)   // 34816
#define SMEM_BYTES (2 * (A_STAGE_B + B_STAGE_B))  // 106496 -> 2 CTAs/SM

#define NSPLIT 4
#define OVF_CAP 2048
#define MW_PLANE (128 * 64 * 16)   // words per metadata candidate layout

// ---- device-global scratch ----
__device__ __align__(256) float    g_W32[OUTF * INF];            // 16 MB dense W accumulator
__device__ __align__(256) __half   g_Wc[OUTF * (INF / 2)];       // 4 MB compressed 2:4 W
__device__ __align__(256) __half   g_Xh[(size_t)NN * INF];       // 256 MB fp16 x
__device__ __align__(256) uint32_t g_Mw[4 * MW_PLANE];           // metadata, 4 candidate layouts
__device__ int      g_ovf_cnt[16];
__device__ float    g_ovf_val[16][OVF_CAP];
__device__ uint32_t g_ovf_ko[16][OVF_CAP];
__device__ int      g_flag;                                       // selected metadata layout

// ---- helpers ----
__device__ __forceinline__ uint32_t smem_u32(const void* p) {
    return (uint32_t)__cvta_generic_to_shared(p);
}
__device__ __forceinline__ void cp16(uint32_t dst, const void* src) {
    asm volatile("cp.async.cg.shared.global [%0], [%1], 16;" :: "r"(dst), "l"(src) : "memory");
}
__device__ __forceinline__ void cp_commit() {
    asm volatile("cp.async.commit_group;" ::: "memory");
}
template <int N>
__device__ __forceinline__ void cp_wait() {
    asm volatile("cp.async.wait_group %0;" :: "n"(N) : "memory");
}
__device__ __forceinline__ void ldsm_x4(uint32_t& r0, uint32_t& r1, uint32_t& r2, uint32_t& r3,
                                        uint32_t addr) {
    asm volatile("ldmatrix.sync.aligned.m8n8.x4.shared.b16 {%0,%1,%2,%3}, [%4];"
                 : "=r"(r0), "=r"(r1), "=r"(r2), "=r"(r3) : "r"(addr));
}
// 2:4 sparse mma: A compressed 16x16 (of 16x32), B 32x8 dense, metadata e, selector 0
__device__ __forceinline__ void mma_sp(float* c, const uint32_t* a,
                                       uint32_t b0, uint32_t b1, uint32_t b2, uint32_t b3,
                                       uint32_t e) {
    asm volatile(
        "mma.sp.sync.aligned.m16n8k32.row.col.f32.f16.f16.f32 "
        "{%0,%1,%2,%3}, {%4,%5,%6,%7}, {%8,%9,%10,%11}, {%0,%1,%2,%3}, %12, 0x0;"
        : "+f"(c[0]), "+f"(c[1]), "+f"(c[2]), "+f"(c[3])
        : "r"(a[0]), "r"(a[1]), "r"(a[2]), "r"(a[3]),
          "r"(b0), "r"(b1), "r"(b2), "r"(b3), "r"(e));
}
__device__ __forceinline__ uint32_t packh2(float lo, float hi) {
    __half2 h = __floats2half2_rn(lo, hi);
    return *reinterpret_cast<uint32_t*>(&h);
}

// ---- prologue kernels ----
__global__ void zero_w_kernel() {
    int i = blockIdx.x * blockDim.x + threadIdx.x;
    reinterpret_cast<float4*>(g_W32)[i] = make_float4(0.f, 0.f, 0.f, 0.f);
    if (blockIdx.x == 0 && threadIdx.x < 16) g_ovf_cnt[threadIdx.x] = 0;
}
__global__ void scatter_kernel(const float* __restrict__ vals, const int* __restrict__ rows,
                               const int* __restrict__ cols) {
    int i = blockIdx.x * blockDim.x + threadIdx.x;
    atomicAdd(&g_W32[rows[i] * INF + cols[i]], vals[i]);
}
// 2:4 compress: one thread per (row o, k32-chunk c). Builds compressed values,
// metadata nibbles (4 candidate register layouts), overflow list.
__global__ void compress_kernel() {
    int t = blockIdx.x * blockDim.x + threadIdx.x;   // 131072
    int o = t >> 6, c = t & 63;
    const float* wrow = g_W32 + o * INF + c * 32;

    __half hc[16];
    uint32_t nib[8];
#pragma unroll
    for (int g = 0; g < 8; g++) {
        float v0 = wrow[4 * g], v1 = wrow[4 * g + 1], v2 = wrow[4 * g + 2], v3 = wrow[4 * g + 3];
        float vv[4] = {v0, v1, v2, v3};
        int idx[2] = {0, 1};
        float val[2] = {0.f, 0.f};
        int cnt = 0;
#pragma unroll
        for (int j = 0; j < 4; j++) {
            if (vv[j] != 0.f) {
                if (cnt < 2) { idx[cnt] = j; val[cnt] = vv[j]; cnt++; }
                else {
                    int b = o >> 7;
                    int s = atomicAdd(&g_ovf_cnt[b], 1);
                    if (s < OVF_CAP) {
                        g_ovf_val[b][s] = vv[j];
                        g_ovf_ko[b][s] = (uint32_t)(c * 32 + g * 4 + j) | ((uint32_t)o << 16);
                    }
                }
            }
        }
        if (cnt == 0) { idx[0] = 0; idx[1] = 1; }
        else if (cnt == 1) {
            int other = (idx[0] + 1) & 3;
            if (other < idx[0]) { idx[1] = idx[0]; val[1] = val[0]; idx[0] = other; val[0] = 0.f; }
            else { idx[1] = other; val[1] = 0.f; }
        }
        nib[g] = (uint32_t)idx[0] | ((uint32_t)idx[1] << 2);
        hc[2 * g]     = __float2half_rn(val[0]);
        hc[2 * g + 1] = __float2half_rn(val[1]);
    }
    // compressed values: 16 halves = 32 B
    *reinterpret_cast<uint4*>(g_Wc + (size_t)o * (INF / 2) + c * 16)     = *reinterpret_cast<uint4*>(hc);
    *reinterpret_cast<uint4*>(g_Wc + (size_t)o * (INF / 2) + c * 16 + 8) = *reinterpret_cast<uint4*>(hc + 8);

    uint32_t lo16 = nib[0] | (nib[1] << 4) | (nib[2] << 8) | (nib[3] << 12);   // groups 0-3 (k[0,16))
    uint32_t hi16 = nib[4] | (nib[5] << 4) | (nib[6] << 8) | (nib[7] << 12);   // groups 4-7 (k[16,32))
    int m16 = o >> 4, r = o & 15, q = r & 7, hi = r >> 3;
    int wbase = ((m16 * 64 + c) * 8 + q) * 2;   // word index (without p)
    uint16_t* M16 = reinterpret_cast<uint16_t*>(g_Mw);
    // cand0 (k-split): p0 = k-lo {row_lo | row_hi<<16}; p1 = k-hi
    M16[(0 * MW_PLANE + wbase + 0) * 2 + hi] = (uint16_t)lo16;
    M16[(0 * MW_PLANE + wbase + 1) * 2 + hi] = (uint16_t)hi16;
    // cand1 (row-split): p0 = row_lo full k32; p1 = row_hi
    g_Mw[1 * MW_PLANE + wbase + hi] = lo16 | (hi16 << 16);
    // cand2 (k-split swapped): p0 = k-hi; p1 = k-lo
    M16[(2 * MW_PLANE + wbase + 0) * 2 + hi] = (uint16_t)hi16;
    M16[(2 * MW_PLANE + wbase + 1) * 2 + hi] = (uint16_t)lo16;
    // cand3 (row-split swapped): p0 = row_hi; p1 = row_lo
    g_Mw[3 * MW_PLANE + wbase + (1 - hi)] = lo16 | (hi16 << 16);
}
// Self-test: discover the hardware metadata layout with a known sparse product.
__global__ void sptest_kernel() {
    int lid = threadIdx.x;
    int p4 = lid & 3;
    uint32_t a[4];
    a[0] = (p4 == 0) ? packh2(2.f, 5.f) : 0u;   // rows 0-7: vals 2@k1, 5@k3
    a[1] = (p4 == 0) ? packh2(3.f, 7.f) : 0u;   // rows 8-15: vals 3@k0, 7@k2
    a[2] = 0u; a[3] = 0u;
    uint32_t b0 = (p4 == 0) ? packh2(1.f, 2.f) : (p4 == 1 ? packh2(4.f, 8.f) : 0u);  // B[k]=2^k, k<4
    // candidate encodings: nibbles row_lo g0=0xD (idx1,3), row_hi g0=0x8 (idx0,2), rest 0x4
    const uint32_t enc[4][2] = {
        {0x4448444Du, 0x44444444u},   // cand0
        {0x4444444Du, 0x44444448u},   // cand1
        {0x44444444u, 0x4448444Du},   // cand2
        {0x44444448u, 0x4444444Du}};  // cand3
    int sel = -1;
#pragma unroll
    for (int cand = 0; cand < 4; cand++) {
        float c[4] = {0.f, 0.f, 0.f, 0.f};
        uint32_t e = enc[cand][lid & 1];
        mma_sp(c, a, b0, 0u, 0u, 0u, e);
        // correct layout: rows 0-7 -> 2*2+5*8=44 ; rows 8-15 -> 3*1+7*4=31 (all cols)
        bool ok = (fabsf(c[0] - 44.f) < 0.5f) && (fabsf(c[2] - 31.f) < 0.5f);
        unsigned m = __ballot_sync(0xFFFFFFFFu, ok);
        if (m == 0xFFFFFFFFu && sel < 0) sel = cand;
    }
    if (lid == 0) g_flag = (sel >= 0) ? sel : 0;
}
__global__ void conv_x_kernel(const float* __restrict__ x) {
    size_t i = (size_t)blockIdx.x * blockDim.x + threadIdx.x;
    float4 v = reinterpret_cast<const float4*>(x)[i];
    union { __half2 h[2]; uint2 u; } p;
    p.h[0] = __floats2half2_rn(v.x, v.y);
    p.h[1] = __floats2half2_rn(v.z, v.w);
    reinterpret_cast<uint2*>(g_Xh)[i] = p.u;
}

// ---- sparse GEMM: out[n,o] = sum_k W[o,k]*x[n,k] + bias[o] ----
__global__ void __launch_bounds__(256, 2)
spgemm_kernel(const float* __restrict__ bias, const float* __restrict__ x,
              float* __restrict__ out, int n_tile_base) {
    extern __shared__ __align__(128) uint8_t smem[];
    uint8_t* sA = smem;                       // 2 * A_STAGE_B
    uint8_t* sB = smem + 2 * A_STAGE_B;       // 2 * B_STAGE_B

    const int tid = threadIdx.x;
    const int wid = tid >> 5;
    const int lid = tid & 31;
    const int wm = wid & 1;
    const int wn = wid >> 1;
    const int m0 = blockIdx.x * TM;
    const int n0 = (n_tile_base + blockIdx.y) * TN;

    const uint32_t sA_base = smem_u32(sA);
    const uint32_t sB_base = smem_u32(sB);
    const int flag = g_flag;
    const uint32_t* Mw = g_Mw + flag * MW_PLANE;
    const int m16base = blockIdx.x * 8 + wm * 4;   // global m16-block of mt=0

    auto load_stage = [&](int stage, int kt) {
        const uint32_t a_dst = sA_base + stage * A_STAGE_B;
        const uint32_t b_dst = sB_base + stage * B_STAGE_B;
#pragma unroll
        for (int i = 0; i < 4; i++) {           // A: 1024 x 16B (rows 128 x 128B compressed)
            int cc = tid + (i << 8);
            int r = cc >> 3, kc = cc & 7;
            cp16(a_dst + r * (ROWH_A * 2) + kc * 16,
                 g_Wc + (size_t)(m0 + r) * (INF / 2) + kt * 64 + kc * 8);
        }
#pragma unroll
        for (int i = 0; i < 8; i++) {           // B: 2048 x 16B (rows 128 x 256B)
            int cc = tid + (i << 8);
            int r = cc >> 4, kc = cc & 15;
            cp16(b_dst + r * (ROWH_B * 2) + kc * 16,
                 g_Xh + (size_t)(n0 + r) * INF + kt * TKO + kc * 8);
        }
        cp_commit();
    };

    load_stage(0, 0);
    load_stage(1, 1);

    float acc[4][4][4];
#pragma unroll
    for (int mt = 0; mt < 4; mt++)
#pragma unroll
        for (int nt = 0; nt < 4; nt++)
#pragma unroll
            for (int e = 0; e < 4; e++) acc[mt][nt][e] = 0.f;

    const int a_row = lid & 15;
    const int a_koff = (lid >> 4) << 3;                  // compressed-half offset 0/8
    const int b_nrow = (lid & 7) + ((lid >> 4) << 3);
    const int b_koff = ((lid >> 3) & 1) << 3;
    const int q = lid >> 2;
    const int p = lid & 1;

    for (int kt = 0; kt < NKSTEPS; kt++) {
        const int stage = kt & 1;
        cp_wait<1>();
        __syncthreads();

        const uint32_t aS = sA_base + stage * A_STAGE_B;
        const uint32_t bS = sB_base + stage * B_STAGE_B;

#pragma unroll
        for (int s = 0; s < 4; s++) {           // four k32 sub-steps per TKO=128
            uint32_t af[4][4], ee[4];
#pragma unroll
            for (int mt = 0; mt < 4; mt++) {
                uint32_t addr = aS + ((wm * 64 + mt * 16 + a_row) * ROWH_A + s * 16 + a_koff) * 2;
                ldsm_x4(af[mt][0], af[mt][1], af[mt][2], af[mt][3], addr);
                ee[mt] = __ldg(&Mw[(((m16base + mt) * 64 + (kt * 4 + s)) * 8 + q) * 2 + p]);
            }
#pragma unroll
            for (int j = 0; j < 2; j++) {       // two n16 groups (n 32)
                uint32_t lo[4], hi[4];
                uint32_t base = bS + ((wn * 32 + j * 16 + b_nrow) * ROWH_B) * 2;
                ldsm_x4(lo[0], lo[1], lo[2], lo[3], base + (s * 32 + b_koff) * 2);
                ldsm_x4(hi[0], hi[1], hi[2], hi[3], base + (s * 32 + 16 + b_koff) * 2);
#pragma unroll
                for (int mt = 0; mt < 4; mt++) {
                    mma_sp(acc[mt][2 * j],     af[mt], lo[0], lo[1], hi[0], hi[1], ee[mt]);
                    mma_sp(acc[mt][2 * j + 1], af[mt], lo[2], lo[3], hi[2], hi[3], ee[mt]);
                }
            }
        }

        __syncthreads();
        if (kt + 2 < NKSTEPS) load_stage(stage, kt + 2);
        else                  cp_commit();       // keep wait-count invariant sound
    }

    // ---- overflow fixup (exact, fused) ----
    const int p2 = (lid & 3) << 1;
    {
        const int bucket = blockIdx.x;
        int cnt = g_ovf_cnt[bucket];
        if (cnt > OVF_CAP) cnt = OVF_CAP;
        for (int e2 = 0; e2 < cnt; e2++) {
            uint32_t ko = g_ovf_ko[bucket][e2];
            float v = g_ovf_val[bucket][e2];
            int o = (int)(ko >> 16), k = (int)(ko & 0xFFFFu);
            int ol = o - m0 - wm * 64;
            if (ol < 0 || ol >= 64) continue;
            int mt = ol >> 4, rem = ol & 15, hp = rem >> 3;
            if ((rem & 7) != q) continue;
#pragma unroll
            for (int nt = 0; nt < 4; nt++) {
                int n = n0 + wn * 32 + nt * 8 + p2;
                float xv0 = x[(size_t)n * INF + k];
                float xv1 = x[(size_t)(n + 1) * INF + k];
                acc[mt][nt][hp * 2]     += v * xv0;
                acc[mt][nt][hp * 2 + 1] += v * xv1;
            }
        }
    }

    // ---- epilogue: out[n, o] += bias[o] ----
#pragma unroll
    for (int mt = 0; mt < 4; mt++) {
        const int o_lo = m0 + wm * 64 + mt * 16 + q;
        const float bv_lo = bias[o_lo];
        const float bv_hi = bias[o_lo + 8];
#pragma unroll
        for (int nt = 0; nt < 4; nt++) {
            const int n = n0 + wn * 32 + nt * 8 + p2;
            float* o0 = out + (size_t)n * OUTF;
            float* o1 = out + (size_t)(n + 1) * OUTF;
            o0[o_lo]     = acc[mt][nt][0] + bv_lo;
            o1[o_lo]     = acc[mt][nt][1] + bv_lo;
            o0[o_lo + 8] = acc[mt][nt][2] + bv_hi;
            o1[o_lo + 8] = acc[mt][nt][3] + bv_hi;
        }
    }
}

extern "C" void kernel_launch(void* const* d_in, const int* in_sizes, int n_in,
                              void* d_out, int out_size) {
    (void)in_sizes; (void)n_in; (void)out_size;
    const float* x      = (const float*)d_in[0];
    const float* values = (const float*)d_in[1];
    const float* bias   = (const float*)d_in[2];
    const int*   rows   = (const int*)d_in[3];
    const int*   cols   = (const int*)d_in[4];
    float* out = (float*)d_out;

    zero_w_kernel<<<(OUTF * INF / 4) / 256, 256>>>();
    scatter_kernel<<<NNZV / 256, 256>>>(values, rows, cols);
    compress_kernel<<<(OUTF * 64) / 256, 256>>>();
    sptest_kernel<<<1, 32>>>();
    conv_x_kernel<<<(int)(((size_t)NN * INF / 4) / 256), 256>>>(x);

    static bool attr_set = false;
    if (!attr_set) {
        cudaFuncSetAttribute(spgemm_kernel, cudaFuncAttributeMaxDynamicSharedMemorySize, SMEM_BYTES);
        attr_set = true;
    }
    const int n_tiles_per_split = (NN / TN) / NSPLIT;   // 128
    for (int s = 0; s < NSPLIT; s++) {
        spgemm_kernel<<<dim3(OUTF / TM, n_tiles_per_split), 256, SMEM_BYTES>>>(
            bias, x, out, s * n_tiles_per_split);
    }
}

// round 8
// speedup vs baseline: 3.8351x; 3.8351x over previous
#include <cuda_runtime.h>
#include <cuda_fp16.h>
#include <cstdint>

#define OUTF 2048
#define INF  2048
#define NNZV 262144
#define NN   65536

#define TM 128        // output tile (A rows)
#define TN 128        // node tile (B rows)
#define TK 32         // halves per K chunk
#define NSTAGE 3
#define NKSTEPS (INF / TK)   // 64

#define ROWH 40       // padded row stride in halves (80 B; conflict-free ldmatrix)
#define STAGE_B (TM * ROWH * 2)                 // 10240 per operand per stage
#define SMEM_BYTES (NSTAGE * 2 * STAGE_B)       // 61440 -> 2 CTAs/SM

#define NSPLIT 4      // gemm split into 4 launches over n (ncu capture targeting)

// ---- device-global scratch ----
__device__ __align__(256) float  g_W32[OUTF * INF];   // 16 MB dense W accumulator
__device__ __align__(256) __half g_W16[OUTF * INF];   // 8 MB fp16 W (L2-resident in GEMM)

// ---- helpers ----
__device__ __forceinline__ uint32_t smem_u32(const void* p) {
    return (uint32_t)__cvta_generic_to_shared(p);
}
__device__ __forceinline__ void cp16(uint32_t dst, const void* src) {
    asm volatile("cp.async.cg.shared.global [%0], [%1], 16;" :: "r"(dst), "l"(src) : "memory");
}
__device__ __forceinline__ void cp_commit() {
    asm volatile("cp.async.commit_group;" ::: "memory");
}
template <int N>
__device__ __forceinline__ void cp_wait() {
    asm volatile("cp.async.wait_group %0;" :: "n"(N) : "memory");
}
__device__ __forceinline__ void ldsm_x4(uint32_t& r0, uint32_t& r1, uint32_t& r2, uint32_t& r3,
                                        uint32_t addr) {
    asm volatile("ldmatrix.sync.aligned.m8n8.x4.shared.b16 {%0,%1,%2,%3}, [%4];"
                 : "=r"(r0), "=r"(r1), "=r"(r2), "=r"(r3) : "r"(addr));
}
__device__ __forceinline__ void mma16816(float* c, const uint32_t* a, uint32_t b0, uint32_t b1) {
    asm volatile(
        "mma.sync.aligned.m16n8k16.row.col.f32.f16.f16.f32 "
        "{%0,%1,%2,%3}, {%4,%5,%6,%7}, {%8,%9}, {%0,%1,%2,%3};"
        : "+f"(c[0]), "+f"(c[1]), "+f"(c[2]), "+f"(c[3])
        : "r"(a[0]), "r"(a[1]), "r"(a[2]), "r"(a[3]), "r"(b0), "r"(b1));
}
__device__ __forceinline__ uint32_t packh2(float lo, float hi) {
    __half2 h = __floats2half2_rn(lo, hi);
    return *reinterpret_cast<uint32_t*>(&h);
}

// ---- prologue kernels ----
__global__ void zero_w_kernel() {
    int i = blockIdx.x * blockDim.x + threadIdx.x;
    reinterpret_cast<float4*>(g_W32)[i] = make_float4(0.f, 0.f, 0.f, 0.f);
}
__global__ void scatter_kernel(const float* __restrict__ vals, const int* __restrict__ rows,
                               const int* __restrict__ cols) {
    int i = blockIdx.x * blockDim.x + threadIdx.x;
    atomicAdd(&g_W32[rows[i] * INF + cols[i]], vals[i]);
}
__global__ void conv_w_kernel() {
    int i = blockIdx.x * blockDim.x + threadIdx.x;  // per float4
    float4 v = reinterpret_cast<const float4*>(g_W32)[i];
    union { __half2 h[2]; uint2 u; } p;
    p.h[0] = __floats2half2_rn(v.x, v.y);
    p.h[1] = __floats2half2_rn(v.z, v.w);
    reinterpret_cast<uint2*>(g_W16)[i] = p.u;
}

// ---- GEMM: out[n, o] = sum_k W[o,k] * x[n,k] + bias[o] ----
// A = fp16 W rows (cp.async). B = fp32 x rows, converted to fp16 IN-KERNEL:
// LDG fp32 at iter top (latency hidden under MMA compute), cvt+STS at iter
// bottom into the 3rd buffer. One __syncthreads per k-iter; every iter
// commits exactly one cp.async group so cp_wait<1> is sound including tail.
__global__ void __launch_bounds__(256, 2)
gemm_kernel(const float* __restrict__ bias, const float* __restrict__ x,
            float* __restrict__ out, int n_tile_base) {
    extern __shared__ __align__(128) uint8_t smem[];
    uint8_t* sA = smem;                         // NSTAGE * STAGE_B
    uint8_t* sB = smem + NSTAGE * STAGE_B;      // NSTAGE * STAGE_B

    const int tid = threadIdx.x;
    const int wid = tid >> 5;
    const int lid = tid & 31;
    const int wm = wid & 1;        // warp M index (2)
    const int wn = wid >> 1;       // warp N index (4)
    const int m0 = blockIdx.x * TM;
    const int n0 = (n_tile_base + blockIdx.y) * TN;

    const uint32_t sA_base = smem_u32(sA);
    const uint32_t sB_base = smem_u32(sB);

    // A stage: 128 rows x 64 B = 512 x 16B chunks; 2 per thread. Commits 1 group.
    auto load_A = [&](int stage, int kt) {
        const uint32_t a_dst = sA_base + stage * STAGE_B;
        const int kh = kt * TK;
#pragma unroll
        for (int i = 0; i < 2; i++) {
            int id = tid + (i << 8);
            int r = id >> 2, c = id & 3;
            cp16(a_dst + r * (ROWH * 2) + c * 16,
                 g_W16 + (size_t)(m0 + r) * INF + kh + c * 8);
        }
        cp_commit();
    };
    // B source coords: thread t covers row (t>>1), 16 floats at (t&1)*16.
    const int br = tid >> 1;
    const int bfo = (tid & 1) << 4;
    auto ldg_B = [&](float4* bf, int kt) {
        const float* src = x + (size_t)(n0 + br) * INF + kt * TK + bfo;
#pragma unroll
        for (int i = 0; i < 4; i++) bf[i] = reinterpret_cast<const float4*>(src)[i];
    };
    auto sts_B = [&](const float4* bf, int stage) {
        uint8_t* dst = sB + stage * STAGE_B + br * (ROWH * 2) + bfo * 2;
        uint4 u0, u1;
        u0.x = packh2(bf[0].x, bf[0].y); u0.y = packh2(bf[0].z, bf[0].w);
        u0.z = packh2(bf[1].x, bf[1].y); u0.w = packh2(bf[1].z, bf[1].w);
        u1.x = packh2(bf[2].x, bf[2].y); u1.y = packh2(bf[2].z, bf[2].w);
        u1.z = packh2(bf[3].x, bf[3].y); u1.w = packh2(bf[3].z, bf[3].w);
        *reinterpret_cast<uint4*>(dst)      = u0;
        *reinterpret_cast<uint4*>(dst + 16) = u1;
    };

    // prologue: A stages 0,1 async; B stages 0,1 blocking (one-time cost)
    load_A(0, 0);
    load_A(1, 1);
    {
        float4 b0[4];
        ldg_B(b0, 0); sts_B(b0, 0);
        ldg_B(b0, 1); sts_B(b0, 1);
    }

    float acc[4][4][4];
#pragma unroll
    for (int mt = 0; mt < 4; mt++)
#pragma unroll
        for (int nt = 0; nt < 4; nt++)
#pragma unroll
            for (int e = 0; e < 4; e++) acc[mt][nt][e] = 0.f;

    const int a_row = lid & 15;
    const int a_koff = (lid >> 4) << 3;
    const int b_nrow = (lid & 7) + ((lid >> 4) << 3);
    const int b_koff = ((lid >> 3) & 1) << 3;

    int stage = 0;
    for (int kt = 0; kt < NKSTEPS; kt++) {
        cp_wait<1>();      // G_kt (A stage kt) resident
        __syncthreads();   // B stage kt STS visible; buffer (kt-1)%3 readers done

        const bool pf = (kt + 2 < NKSTEPS);
        int pstage = stage + 2; if (pstage >= NSTAGE) pstage -= NSTAGE;
        float4 bf[4];
        if (pf) {
            ldg_B(bf, kt + 2);     // fp32 loads in flight during compute below
            load_A(pstage, kt + 2);
        } else {
            cp_commit();           // empty group keeps wait-count sound
        }

        const uint32_t aS = sA_base + stage * STAGE_B;
        const uint32_t bS = sB_base + stage * STAGE_B;

#pragma unroll
        for (int ks = 0; ks < 2; ks++) {        // two k16 steps per TK=32
            uint32_t af[4][4], bfr[2][4];
#pragma unroll
            for (int mt = 0; mt < 4; mt++) {
                uint32_t addr = aS + ((wm * 64 + mt * 16 + a_row) * ROWH + ks * 16 + a_koff) * 2;
                ldsm_x4(af[mt][0], af[mt][1], af[mt][2], af[mt][3], addr);
            }
#pragma unroll
            for (int j = 0; j < 2; j++) {
                uint32_t addr = bS + ((wn * 32 + j * 16 + b_nrow) * ROWH + ks * 16 + b_koff) * 2;
                ldsm_x4(bfr[j][0], bfr[j][1], bfr[j][2], bfr[j][3], addr);
            }
#pragma unroll
            for (int mt = 0; mt < 4; mt++)
#pragma unroll
                for (int j = 0; j < 2; j++) {
                    mma16816(acc[mt][2 * j],     af[mt], bfr[j][0], bfr[j][1]);
                    mma16816(acc[mt][2 * j + 1], af[mt], bfr[j][2], bfr[j][3]);
                }
        }

        if (pf) sts_B(bf, pstage);   // cvt+store after compute (LDG long returned)

        if (++stage >= NSTAGE) stage = 0;
    }

    // ---- epilogue: out[n, o] += bias[o] ----
    const int q = lid >> 2;
    const int p2 = (lid & 3) << 1;
#pragma unroll
    for (int mt = 0; mt < 4; mt++) {
        const int o_lo = m0 + wm * 64 + mt * 16 + q;
        const float bv_lo = bias[o_lo];
        const float bv_hi = bias[o_lo + 8];
#pragma unroll
        for (int nt = 0; nt < 4; nt++) {
            const int n = n0 + wn * 32 + nt * 8 + p2;
            float* o0 = out + (size_t)n * OUTF;
            float* o1 = out + (size_t)(n + 1) * OUTF;
            o0[o_lo]     = acc[mt][nt][0] + bv_lo;
            o1[o_lo]     = acc[mt][nt][1] + bv_lo;
            o0[o_lo + 8] = acc[mt][nt][2] + bv_hi;
            o1[o_lo + 8] = acc[mt][nt][3] + bv_hi;
        }
    }
}

extern "C" void kernel_launch(void* const* d_in, const int* in_sizes, int n_in,
                              void* d_out, int out_size) {
    (void)in_sizes; (void)n_in; (void)out_size;
    const float* x      = (const float*)d_in[0];
    const float* values = (const float*)d_in[1];
    const float* bias   = (const float*)d_in[2];
    const int*   rows   = (const int*)d_in[3];
    const int*   cols   = (const int*)d_in[4];
    float* out = (float*)d_out;

    zero_w_kernel<<<(OUTF * INF / 4) / 256, 256>>>();
    scatter_kernel<<<NNZV / 256, 256>>>(values, rows, cols);
    conv_w_kernel<<<(OUTF * INF / 4) / 256, 256>>>();

    static bool attr_set = false;
    if (!attr_set) {
        cudaFuncSetAttribute(gemm_kernel, cudaFuncAttributeMaxDynamicSharedMemorySize, SMEM_BYTES);
        attr_set = true;
    }
    const int n_tiles_per_split = (NN / TN) / NSPLIT;   // 128
    for (int s = 0; s < NSPLIT; s++) {
        gemm_kernel<<<dim3(OUTF / TM, n_tiles_per_split), 256, SMEM_BYTES>>>(
            bias, x, out, s * n_tiles_per_split);
    }
}

// round 9
// speedup vs baseline: 5.6775x; 1.4804x over previous
#include <cuda_runtime.h>
#include <cuda_fp16.h>
#include <cstdint>

#define OUTF 2048
#define INF  2048
#define NNZV 262144
#define NN   65536

#define TM 128        // output tile
#define TN 128        // node tile
#define TK 64         // halves per K chunk (4 k16 sub-steps)
#define NSTAGE 3
#define NKSTEPS (INF / TK)   // 32
#define NK16 (INF / 16)      // 128

#define ROWH 72       // B smem row stride in halves (144 B = 9*16B -> conflict-free ldmatrix)
#define B_STAGE_B (TN * ROWH * 2)              // 18432
#define SMEM_BYTES (NSTAGE * B_STAGE_B)        // 55296 -> 2 CTAs/SM easily

#define NSPLIT 4

// ---- device-global scratch ----
__device__ __align__(256) float  g_W32[OUTF * INF];               // 16 MB dense W accumulator
__device__ __align__(256) uint4  g_Wfrag[(OUTF / 16) * NK16 * 32]; // 8 MB fragment-major fp16 W
__device__ __align__(256) __half g_Xh[(size_t)NN * INF];          // 256 MB fp16 x

// ---- helpers ----
__device__ __forceinline__ uint32_t smem_u32(const void* p) {
    return (uint32_t)__cvta_generic_to_shared(p);
}
__device__ __forceinline__ void cp16(uint32_t dst, const void* src) {
    asm volatile("cp.async.cg.shared.global [%0], [%1], 16;" :: "r"(dst), "l"(src) : "memory");
}
__device__ __forceinline__ void cp_commit() {
    asm volatile("cp.async.commit_group;" ::: "memory");
}
template <int N>
__device__ __forceinline__ void cp_wait() {
    asm volatile("cp.async.wait_group %0;" :: "n"(N) : "memory");
}
__device__ __forceinline__ void ldsm_x4(uint32_t& r0, uint32_t& r1, uint32_t& r2, uint32_t& r3,
                                        uint32_t addr) {
    asm volatile("ldmatrix.sync.aligned.m8n8.x4.shared.b16 {%0,%1,%2,%3}, [%4];"
                 : "=r"(r0), "=r"(r1), "=r"(r2), "=r"(r3) : "r"(addr));
}
__device__ __forceinline__ void mma16816(float* c, const uint4& a, uint32_t b0, uint32_t b1) {
    asm volatile(
        "mma.sync.aligned.m16n8k16.row.col.f32.f16.f16.f32 "
        "{%0,%1,%2,%3}, {%4,%5,%6,%7}, {%8,%9}, {%0,%1,%2,%3};"
        : "+f"(c[0]), "+f"(c[1]), "+f"(c[2]), "+f"(c[3])
        : "r"(a.x), "r"(a.y), "r"(a.z), "r"(a.w), "r"(b0), "r"(b1));
}
__device__ __forceinline__ uint32_t packh2(float lo, float hi) {
    __half2 h = __floats2half2_rn(lo, hi);
    return *reinterpret_cast<uint32_t*>(&h);
}

// ---- prologue kernels ----
__global__ void zero_w_kernel() {
    int i = blockIdx.x * blockDim.x + threadIdx.x;
    reinterpret_cast<float4*>(g_W32)[i] = make_float4(0.f, 0.f, 0.f, 0.f);
}
__global__ void scatter_kernel(const float* __restrict__ vals, const int* __restrict__ rows,
                               const int* __restrict__ cols) {
    int i = blockIdx.x * blockDim.x + threadIdx.x;
    atomicAdd(&g_W32[rows[i] * INF + cols[i]], vals[i]);
}
// Pack W into mma.m16n8k16 A-fragment layout: lane l of tile (T=m16, K=k16) holds
//  a0 = A[T*16 + l/4][K*16 + (l%4)*2 .. +1]
//  a1 = A[.. +8 row][..]   a2 = A[row][k+8 ..]   a3 = A[row+8][k+8 ..]
__global__ void pack_frag_kernel() {
    int t = blockIdx.x * blockDim.x + threadIdx.x;   // 524288
    int lane = t & 31;
    int kk = (t >> 5) & (NK16 - 1);
    int T = t >> 12;
    int r0 = T * 16 + (lane >> 2);
    int kb = kk * 16 + (lane & 3) * 2;
    const float* W = g_W32;
    uint4 f;
    f.x = packh2(W[r0 * INF + kb],            W[r0 * INF + kb + 1]);
    f.y = packh2(W[(r0 + 8) * INF + kb],      W[(r0 + 8) * INF + kb + 1]);
    f.z = packh2(W[r0 * INF + kb + 8],        W[r0 * INF + kb + 9]);
    f.w = packh2(W[(r0 + 8) * INF + kb + 8],  W[(r0 + 8) * INF + kb + 9]);
    g_Wfrag[t] = f;
}
__global__ void conv_x_kernel(const float* __restrict__ x) {
    size_t i = (size_t)blockIdx.x * blockDim.x + threadIdx.x;
    float4 v = reinterpret_cast<const float4*>(x)[i];
    union { __half2 h[2]; uint2 u; } p;
    p.h[0] = __floats2half2_rn(v.x, v.y);
    p.h[1] = __floats2half2_rn(v.z, v.w);
    reinterpret_cast<uint2*>(g_Xh)[i] = p.u;
}

// ---- GEMM: out[n, o] = sum_k W[o,k] * x[n,k] + bias[o] ----
// A: fragment-major LDG.128 straight into registers (L2-resident, ring-prefetched
// one k16 ahead). B: fp16 x rows via 3-stage cp.async + ldmatrix. Only B touches
// smem -> smem crossbar load drops to 1KB/warp/k16 (< tensor floor).
__global__ void __launch_bounds__(256, 2)
gemm_kernel(const float* __restrict__ bias, float* __restrict__ out, int n_tile_base) {
    extern __shared__ __align__(128) uint8_t smem[];
    uint8_t* sB = smem;

    const int tid = threadIdx.x;
    const int wid = tid >> 5;
    const int lid = tid & 31;
    const int wm = wid & 1;
    const int wn = wid >> 1;
    const int m0 = blockIdx.x * TM;
    const int n0 = (n_tile_base + blockIdx.y) * TN;

    const uint32_t sB_base = smem_u32(sB);
    const int m16b = blockIdx.x * 8 + wm * 4;   // first m16-tile of this warp

    // B stage: 128 rows x 128 B = 1024 x 16B chunks; 4 per thread. Commits 1 group.
    auto load_B = [&](int stage, int kt) {
        const uint32_t b_dst = sB_base + stage * B_STAGE_B;
        const int kh = kt * TK;
#pragma unroll
        for (int i = 0; i < 4; i++) {
            int c = tid + (i << 8);
            int r = c >> 3, kc = c & 7;
            cp16(b_dst + r * (ROWH * 2) + kc * 16,
                 g_Xh + (size_t)(n0 + r) * INF + kh + kc * 8);
        }
        cp_commit();
    };
    // A fragments: 4 m16-tiles for one k16 step, one LDG.128 each.
    auto ldg_af = [&](uint4* dst, int kk) {
#pragma unroll
        for (int mt = 0; mt < 4; mt++)
            dst[mt] = __ldg(&g_Wfrag[((size_t)(m16b + mt) * NK16 + kk) * 32 + lid]);
    };

    load_B(0, 0);
    load_B(1, 1);

    float acc[4][4][4];
#pragma unroll
    for (int mt = 0; mt < 4; mt++)
#pragma unroll
        for (int nt = 0; nt < 4; nt++)
#pragma unroll
            for (int e = 0; e < 4; e++) acc[mt][nt][e] = 0.f;

    const int b_nrow = (lid & 7) + ((lid >> 4) << 3);
    const int b_koff = ((lid >> 3) & 1) << 3;

    uint4 afA[4], afB[4];
    ldg_af(afA, 0);   // kk=0 in flight before first iteration

    int stage = 0;
    for (int kt = 0; kt < NKSTEPS; kt++) {
        cp_wait<1>();      // B stage kt resident
        __syncthreads();   // + buffer (kt-1)%3 readers done

        if (kt + 2 < NKSTEPS) {
            int pstage = stage + 2; if (pstage >= NSTAGE) pstage -= NSTAGE;
            load_B(pstage, kt + 2);
        } else {
            cp_commit();   // empty group keeps wait-count sound
        }

        const uint32_t bS = sB_base + stage * B_STAGE_B;

#pragma unroll
        for (int ks = 0; ks < 4; ks++) {        // four k16 steps per TK=64
            const int kk = kt * 4 + ks;
            // ring prefetch: next k16's A fragments (distance-1, hides L2 latency)
            int nk = kk + 1; if (nk >= NK16) nk = NK16 - 1;
            if ((ks & 1) == 0) ldg_af(afB, nk); else ldg_af(afA, nk);
            const uint4* af = ((ks & 1) == 0) ? afA : afB;

            uint32_t bfr[2][4];
#pragma unroll
            for (int j = 0; j < 2; j++) {
                uint32_t addr = bS + ((wn * 32 + j * 16 + b_nrow) * ROWH + ks * 16 + b_koff) * 2;
                ldsm_x4(bfr[j][0], bfr[j][1], bfr[j][2], bfr[j][3], addr);
            }
#pragma unroll
            for (int mt = 0; mt < 4; mt++)
#pragma unroll
                for (int j = 0; j < 2; j++) {
                    mma16816(acc[mt][2 * j],     af[mt], bfr[j][0], bfr[j][1]);
                    mma16816(acc[mt][2 * j + 1], af[mt], bfr[j][2], bfr[j][3]);
                }
        }

        if (++stage >= NSTAGE) stage = 0;
    }

    // ---- epilogue: out[n, o] += bias[o] ----
    const int q = lid >> 2;
    const int p2 = (lid & 3) << 1;
#pragma unroll
    for (int mt = 0; mt < 4; mt++) {
        const int o_lo = m0 + wm * 64 + mt * 16 + q;
        const float bv_lo = bias[o_lo];
        const float bv_hi = bias[o_lo + 8];
#pragma unroll
        for (int nt = 0; nt < 4; nt++) {
            const int n = n0 + wn * 32 + nt * 8 + p2;
            float* o0 = out + (size_t)n * OUTF;
            float* o1 = out + (size_t)(n + 1) * OUTF;
            o0[o_lo]     = acc[mt][nt][0] + bv_lo;
            o1[o_lo]     = acc[mt][nt][1] + bv_lo;
            o0[o_lo + 8] = acc[mt][nt][2] + bv_hi;
            o1[o_lo + 8] = acc[mt][nt][3] + bv_hi;
        }
    }
}

extern "C" void kernel_launch(void* const* d_in, const int* in_sizes, int n_in,
                              void* d_out, int out_size) {
    (void)in_sizes; (void)n_in; (void)out_size;
    const float* x      = (const float*)d_in[0];
    const float* values = (const float*)d_in[1];
    const float* bias   = (const float*)d_in[2];
    const int*   rows   = (const int*)d_in[3];
    const int*   cols   = (const int*)d_in[4];
    float* out = (float*)d_out;

    zero_w_kernel<<<(OUTF * INF / 4) / 256, 256>>>();
    scatter_kernel<<<NNZV / 256, 256>>>(values, rows, cols);
    pack_frag_kernel<<<((OUTF / 16) * NK16 * 32) / 256, 256>>>();
    conv_x_kernel<<<(int)(((size_t)NN * INF / 4) / 256), 256>>>(x);

    static bool attr_set = false;
    if (!attr_set) {
        cudaFuncSetAttribute(gemm_kernel, cudaFuncAttributeMaxDynamicSharedMemorySize, SMEM_BYTES);
        attr_set = true;
    }
    const int n_tiles_per_split = (NN / TN) / NSPLIT;   // 128
    for (int s = 0; s < NSPLIT; s++) {
        gemm_kernel<<<dim3(OUTF / TM, n_tiles_per_split), 256, SMEM_BYTES>>>(
            bias, out, s * n_tiles_per_split);
    }
}

// round 10
// speedup vs baseline: 6.1091x; 1.0760x over previous
#include <cuda_runtime.h>
#include <cuda_fp16.h>
#include <cstdint>

#define OUTF 2048
#define INF  2048
#define NNZV 262144
#define NN   65536

#define NK16 (INF / 16)      // 128 k16 steps
#define NM16 (OUTF / 16)     // 128 m16 tiles
#define NN16 (NN / 16)       // 4096 n16 tiles

#define NSPLIT 4             // gemm split over n (also ncu capture targeting)

// ---- device-global scratch ----
__device__ __align__(256) float g_W32[OUTF * INF];                 // 16 MB dense W accumulator
__device__ __align__(256) uint4 g_Wfrag[NM16 * NK16 * 32];         // 8 MB A-fragment-major W
__device__ __align__(256) uint4 g_Xf[(size_t)NN16 * NK16 * 32];    // 256 MB B-fragment-major x

// ---- helpers ----
__device__ __forceinline__ void mma16816(float* c, const uint4& a, uint32_t b0, uint32_t b1) {
    asm volatile(
        "mma.sync.aligned.m16n8k16.row.col.f32.f16.f16.f32 "
        "{%0,%1,%2,%3}, {%4,%5,%6,%7}, {%8,%9}, {%0,%1,%2,%3};"
        : "+f"(c[0]), "+f"(c[1]), "+f"(c[2]), "+f"(c[3])
        : "r"(a.x), "r"(a.y), "r"(a.z), "r"(a.w), "r"(b0), "r"(b1));
}
__device__ __forceinline__ uint32_t packh2(float lo, float hi) {
    __half2 h = __floats2half2_rn(lo, hi);
    return *reinterpret_cast<uint32_t*>(&h);
}

// ---- prologue kernels ----
__global__ void zero_w_kernel() {
    int i = blockIdx.x * blockDim.x + threadIdx.x;
    reinterpret_cast<float4*>(g_W32)[i] = make_float4(0.f, 0.f, 0.f, 0.f);
}
__global__ void scatter_kernel(const float* __restrict__ vals, const int* __restrict__ rows,
                               const int* __restrict__ cols) {
    int i = blockIdx.x * blockDim.x + threadIdx.x;
    atomicAdd(&g_W32[rows[i] * INF + cols[i]], vals[i]);
}
// A-fragment pack (mma.m16n8k16 row-major A): lane l of tile (T=m16, kk) holds
//   x: A[T*16+l/4][kk*16+(l%4)*2 ..+1]   y: same +8 rows
//   z: A[row][k+8..+9]                   w: row+8, k+8
__global__ void pack_w_kernel() {
    int t = blockIdx.x * blockDim.x + threadIdx.x;   // NM16*NK16*32
    int lane = t & 31;
    int kk = (t >> 5) & (NK16 - 1);
    int T = t >> 12;
    int r0 = T * 16 + (lane >> 2);
    int kb = kk * 16 + (lane & 3) * 2;
    const float* W = g_W32;
    uint4 f;
    f.x = packh2(W[r0 * INF + kb],           W[r0 * INF + kb + 1]);
    f.y = packh2(W[(r0 + 8) * INF + kb],     W[(r0 + 8) * INF + kb + 1]);
    f.z = packh2(W[r0 * INF + kb + 8],       W[r0 * INF + kb + 9]);
    f.w = packh2(W[(r0 + 8) * INF + kb + 8], W[(r0 + 8) * INF + kb + 9]);
    g_Wfrag[t] = f;
}
// B-fragment pack (col-major B = x rows as columns): lane l of tile (t=n16, kk):
//   x: {x[n=t*16+l/4][kk*16+(l%4)*2], +1}    y: same col, k+8
//   z: col +8, k lo                          w: col +8, k+8
__global__ void pack_x_kernel(const float* __restrict__ x) {
    size_t t = (size_t)blockIdx.x * blockDim.x + threadIdx.x;   // NN16*NK16*32
    int lane = (int)(t & 31);
    int kk = (int)((t >> 5) & (NK16 - 1));
    int nt = (int)(t >> 12);
    int c0 = nt * 16 + (lane >> 2);
    int kb = kk * 16 + (lane & 3) * 2;
    uint4 f;
    f.x = packh2(x[(size_t)c0 * INF + kb],           x[(size_t)c0 * INF + kb + 1]);
    f.y = packh2(x[(size_t)c0 * INF + kb + 8],       x[(size_t)c0 * INF + kb + 9]);
    f.z = packh2(x[(size_t)(c0 + 8) * INF + kb],     x[(size_t)(c0 + 8) * INF + kb + 1]);
    f.w = packh2(x[(size_t)(c0 + 8) * INF + kb + 8], x[(size_t)(c0 + 8) * INF + kb + 9]);
    g_Xf[t] = f;
}

// ---- GEMM: out[n, o] = sum_k W[o,k] * x[n,k] + bias[o] ----
// Pure register pipeline: both operands fragment-major in gmem, LDG.128 direct
// to registers (L2-resident), double-buffered at distance 1. No smem, no
// syncthreads, no cp.async. 4 warps/CTA, warp tile 64x64, 2 CTAs/SM.
__global__ void __launch_bounds__(128, 2)
gemm_kernel(const float* __restrict__ bias, float* __restrict__ out, int n_tile_base) {
    const int tid = threadIdx.x;
    const int wid = tid >> 5;
    const int lid = tid & 31;
    const int wm = wid & 1;        // 2 m-groups
    const int wn = wid >> 1;       // 2 n-groups
    const int m0 = blockIdx.x * 128;
    const int n0 = (n_tile_base + blockIdx.y) * 128;

    const int m16b = blockIdx.x * 8 + wm * 4;                 // 4 m16 tiles
    const int n16b = (n_tile_base + blockIdx.y) * 8 + wn * 4; // 4 n16 tiles

    const uint4* __restrict__ Aptr = g_Wfrag + ((size_t)m16b * NK16) * 32 + lid;
    const uint4* __restrict__ Bptr = g_Xf   + ((size_t)n16b * NK16) * 32 + lid;
#define ALD(mt, kk) __ldg(Aptr + ((size_t)(mt) * NK16 + (kk)) * 32)
#define BLD(j, kk)  __ldg(Bptr + ((size_t)(j)  * NK16 + (kk)) * 32)

    float acc[4][8][4];
#pragma unroll
    for (int mt = 0; mt < 4; mt++)
#pragma unroll
        for (int nt = 0; nt < 8; nt++)
#pragma unroll
            for (int e = 0; e < 4; e++) acc[mt][nt][e] = 0.f;

    uint4 a0[4], b0[4], a1[4], b1[4];
#pragma unroll
    for (int i = 0; i < 4; i++) { a0[i] = ALD(i, 0); b0[i] = BLD(i, 0); }

#pragma unroll 1
    for (int kk = 0; kk < NK16; kk += 2) {
        // even step: consume buf0, prefetch kk+1 into buf1
        if (kk + 1 < NK16) {
#pragma unroll
            for (int i = 0; i < 4; i++) { a1[i] = ALD(i, kk + 1); b1[i] = BLD(i, kk + 1); }
        }
#pragma unroll
        for (int mt = 0; mt < 4; mt++)
#pragma unroll
            for (int j = 0; j < 4; j++) {
                mma16816(acc[mt][2 * j],     a0[mt], b0[j].x, b0[j].y);
                mma16816(acc[mt][2 * j + 1], a0[mt], b0[j].z, b0[j].w);
            }
        // odd step: consume buf1, prefetch kk+2 into buf0
        if (kk + 2 < NK16) {
#pragma unroll
            for (int i = 0; i < 4; i++) { a0[i] = ALD(i, kk + 2); b0[i] = BLD(i, kk + 2); }
        }
#pragma unroll
        for (int mt = 0; mt < 4; mt++)
#pragma unroll
            for (int j = 0; j < 4; j++) {
                mma16816(acc[mt][2 * j],     a1[mt], b1[j].x, b1[j].y);
                mma16816(acc[mt][2 * j + 1], a1[mt], b1[j].z, b1[j].w);
            }
    }
#undef ALD
#undef BLD

    // ---- epilogue: out[n, o] = acc + bias[o] ----
    const int q = lid >> 2;         // 0..7 (row within m8)
    const int p2 = (lid & 3) << 1;  // 0,2,4,6 (col pair)
#pragma unroll
    for (int mt = 0; mt < 4; mt++) {
        const int o_lo = m0 + wm * 64 + mt * 16 + q;
        const float bv_lo = bias[o_lo];
        const float bv_hi = bias[o_lo + 8];
#pragma unroll
        for (int j = 0; j < 4; j++)
#pragma unroll
            for (int h = 0; h < 2; h++) {
                const int n = n0 + wn * 64 + j * 16 + h * 8 + p2;
                float* o0 = out + (size_t)n * OUTF;
                float* o1 = out + (size_t)(n + 1) * OUTF;
                const float* c = acc[mt][2 * j + h];
                o0[o_lo]     = c[0] + bv_lo;
                o1[o_lo]     = c[1] + bv_lo;
                o0[o_lo + 8] = c[2] + bv_hi;
                o1[o_lo + 8] = c[3] + bv_hi;
            }
    }
}

extern "C" void kernel_launch(void* const* d_in, const int* in_sizes, int n_in,
                              void* d_out, int out_size) {
    (void)in_sizes; (void)n_in; (void)out_size;
    const float* x      = (const float*)d_in[0];
    const float* values = (const float*)d_in[1];
    const float* bias   = (const float*)d_in[2];
    const int*   rows   = (const int*)d_in[3];
    const int*   cols   = (const int*)d_in[4];
    float* out = (float*)d_out;

    zero_w_kernel<<<(OUTF * INF / 4) / 256, 256>>>();
    scatter_kernel<<<NNZV / 256, 256>>>(values, rows, cols);
    pack_w_kernel<<<(NM16 * NK16 * 32) / 256, 256>>>();
    pack_x_kernel<<<(int)(((size_t)NN16 * NK16 * 32) / 256), 256>>>(x);

    const int n_tiles_per_split = (NN / 128) / NSPLIT;   // 128
    for (int s = 0; s < NSPLIT; s++) {
        gemm_kernel<<<dim3(OUTF / 128, n_tiles_per_split), 128>>>(
            bias, out, s * n_tiles_per_split);
    }
}

// round 11
// speedup vs baseline: 6.4612x; 1.0576x over previous
#include <cuda_runtime.h>
#include <cuda_fp16.h>
#include <cstdint>

#define OUTF 2048
#define INF  2048
#define NNZV 262144
#define NN   65536

#define NK16 (INF / 16)      // 128 k16 steps
#define NM16 (OUTF / 16)     // 128 m16 tiles
#define NN16 (NN / 16)       // 4096 n16 tiles

#define NSPLIT 4             // gemm split over n (ncu capture targeting)

// ---- device-global scratch ----
__device__ __align__(256) float g_W32[OUTF * INF];                 // 16 MB dense W accumulator
__device__ __align__(256) uint4 g_Wfrag[NM16 * NK16 * 32];         // 8 MB A-fragment-major W
__device__ __align__(256) uint4 g_Xf[(size_t)NN16 * NK16 * 32];    // 256 MB B-fragment-major x

// ---- helpers ----
__device__ __forceinline__ void mma16816(float* c, const uint4& a, uint32_t b0, uint32_t b1) {
    asm volatile(
        "mma.sync.aligned.m16n8k16.row.col.f32.f16.f16.f32 "
        "{%0,%1,%2,%3}, {%4,%5,%6,%7}, {%8,%9}, {%0,%1,%2,%3};"
        : "+f"(c[0]), "+f"(c[1]), "+f"(c[2]), "+f"(c[3])
        : "r"(a.x), "r"(a.y), "r"(a.z), "r"(a.w), "r"(b0), "r"(b1));
}
__device__ __forceinline__ uint32_t packh2(float lo, float hi) {
    __half2 h = __floats2half2_rn(lo, hi);
    return *reinterpret_cast<uint32_t*>(&h);
}

// ---- prologue kernels ----
__global__ void zero_w_kernel() {
    int i = blockIdx.x * blockDim.x + threadIdx.x;
    reinterpret_cast<float4*>(g_W32)[i] = make_float4(0.f, 0.f, 0.f, 0.f);
}
__global__ void scatter_kernel(const float* __restrict__ vals, const int* __restrict__ rows,
                               const int* __restrict__ cols) {
    int i = blockIdx.x * blockDim.x + threadIdx.x;
    atomicAdd(&g_W32[rows[i] * INF + cols[i]], vals[i]);
}
// A-fragment pack (mma.m16n8k16 row-major A): lane l of tile (T=m16, kk) holds
//   x: A[T*16+l/4][kk*16+(l%4)*2 ..+1]   y: same +8 rows
//   z: A[row][k+8..+9]                   w: row+8, k+8
__global__ void pack_w_kernel() {
    int t = blockIdx.x * blockDim.x + threadIdx.x;   // NM16*NK16*32
    int lane = t & 31;
    int kk = (t >> 5) & (NK16 - 1);
    int T = t >> 12;
    int r0 = T * 16 + (lane >> 2);
    int kb = kk * 16 + (lane & 3) * 2;
    const float* W = g_W32;
    uint4 f;
    f.x = packh2(W[r0 * INF + kb],           W[r0 * INF + kb + 1]);
    f.y = packh2(W[(r0 + 8) * INF + kb],     W[(r0 + 8) * INF + kb + 1]);
    f.z = packh2(W[r0 * INF + kb + 8],       W[r0 * INF + kb + 9]);
    f.w = packh2(W[(r0 + 8) * INF + kb + 8], W[(r0 + 8) * INF + kb + 9]);
    g_Wfrag[t] = f;
}
// B-fragment pack (col-major B = x rows as columns): lane l of tile (t=n16, kk):
//   x: {x[n=t*16+l/4][kk*16+(l%4)*2], +1}    y: same col, k+8
//   z: col +8, k lo                          w: col +8, k+8
__global__ void pack_x_kernel(const float* __restrict__ x) {
    size_t t = (size_t)blockIdx.x * blockDim.x + threadIdx.x;   // NN16*NK16*32
    int lane = (int)(t & 31);
    int kk = (int)((t >> 5) & (NK16 - 1));
    int nt = (int)(t >> 12);
    int c0 = nt * 16 + (lane >> 2);
    int kb = kk * 16 + (lane & 3) * 2;
    uint4 f;
    f.x = packh2(x[(size_t)c0 * INF + kb],           x[(size_t)c0 * INF + kb + 1]);
    f.y = packh2(x[(size_t)c0 * INF + kb + 8],       x[(size_t)c0 * INF + kb + 9]);
    f.z = packh2(x[(size_t)(c0 + 8) * INF + kb],     x[(size_t)(c0 + 8) * INF + kb + 1]);
    f.w = packh2(x[(size_t)(c0 + 8) * INF + kb + 8], x[(size_t)(c0 + 8) * INF + kb + 9]);
    g_Xf[t] = f;
}

// ---- GEMM: out[n, o] = sum_k W[o,k] * x[n,k] + bias[o] ----
// Pure register pipeline, fragment-major LDG.128 operands (L2-resident),
// THREE register buffer sets with prefetch distance 2 (covers ~250cyc L2 hit
// latency; distance-1 in R10 exposed ~85 cyc/iter). Fully unrolled x3 so all
// stage indices are compile-time (no dynamic-index spills).
__global__ void __launch_bounds__(128, 2)
gemm_kernel(const float* __restrict__ bias, float* __restrict__ out, int n_tile_base) {
    const int lid = threadIdx.x & 31;
    const int wid = threadIdx.x >> 5;
    const int wm = wid & 1;        // 2 m-groups
    const int wn = wid >> 1;       // 2 n-groups
    const int m0 = blockIdx.x * 128;
    const int n0 = (n_tile_base + blockIdx.y) * 128;

    const int m16b = blockIdx.x * 8 + wm * 4;
    const int n16b = (n_tile_base + blockIdx.y) * 8 + wn * 4;

    const uint4* __restrict__ Aptr = g_Wfrag + ((size_t)m16b * NK16) * 32 + lid;
    const uint4* __restrict__ Bptr = g_Xf   + ((size_t)n16b * NK16) * 32 + lid;
#define ALD(mt, kk) __ldg(Aptr + ((size_t)(mt) * NK16 + (kk)) * 32)
#define BLD(j, kk)  __ldg(Bptr + ((size_t)(j)  * NK16 + (kk)) * 32)

    float acc[4][8][4];
#pragma unroll
    for (int mt = 0; mt < 4; mt++)
#pragma unroll
        for (int nt = 0; nt < 8; nt++)
#pragma unroll
            for (int e = 0; e < 4; e++) acc[mt][nt][e] = 0.f;

    uint4 a0[4], b0[4], a1[4], b1[4], a2[4], b2[4];
#pragma unroll
    for (int i = 0; i < 4; i++) { a0[i] = ALD(i, 0); b0[i] = BLD(i, 0); }
#pragma unroll
    for (int i = 0; i < 4; i++) { a1[i] = ALD(i, 1); b1[i] = BLD(i, 1); }

    auto consume = [&](const uint4* a, const uint4* b) {
#pragma unroll
        for (int mt = 0; mt < 4; mt++)
#pragma unroll
            for (int j = 0; j < 4; j++) {
                mma16816(acc[mt][2 * j],     a[mt], b[j].x, b[j].y);
                mma16816(acc[mt][2 * j + 1], a[mt], b[j].z, b[j].w);
            }
    };

    // NK16 = 128: kk = 0,3,...,126; tail handled by guards (cheap, uniform).
#pragma unroll 1
    for (int kk = 0; kk < NK16; kk += 3) {
        if (kk + 2 < NK16) {
#pragma unroll
            for (int i = 0; i < 4; i++) { a2[i] = ALD(i, kk + 2); b2[i] = BLD(i, kk + 2); }
        }
        consume(a0, b0);
        if (kk + 3 < NK16) {
#pragma unroll
            for (int i = 0; i < 4; i++) { a0[i] = ALD(i, kk + 3); b0[i] = BLD(i, kk + 3); }
        }
        if (kk + 1 < NK16) consume(a1, b1);
        if (kk + 4 < NK16) {
#pragma unroll
            for (int i = 0; i < 4; i++) { a1[i] = ALD(i, kk + 4); b1[i] = BLD(i, kk + 4); }
        }
        if (kk + 2 < NK16) consume(a2, b2);
    }
#undef ALD
#undef BLD

    // ---- epilogue: out[n, o] = acc + bias[o] ----
    const int q = lid >> 2;
    const int p2 = (lid & 3) << 1;
#pragma unroll
    for (int mt = 0; mt < 4; mt++) {
        const int o_lo = m0 + wm * 64 + mt * 16 + q;
        const float bv_lo = bias[o_lo];
        const float bv_hi = bias[o_lo + 8];
#pragma unroll
        for (int j = 0; j < 4; j++)
#pragma unroll
            for (int h = 0; h < 2; h++) {
                const int n = n0 + wn * 64 + j * 16 + h * 8 + p2;
                float* o0 = out + (size_t)n * OUTF;
                float* o1 = out + (size_t)(n + 1) * OUTF;
                const float* c = acc[mt][2 * j + h];
                o0[o_lo]     = c[0] + bv_lo;
                o1[o_lo]     = c[1] + bv_lo;
                o0[o_lo + 8] = c[2] + bv_hi;
                o1[o_lo + 8] = c[3] + bv_hi;
            }
    }
}

extern "C" void kernel_launch(void* const* d_in, const int* in_sizes, int n_in,
                              void* d_out, int out_size) {
    (void)in_sizes; (void)n_in; (void)out_size;
    const float* x      = (const float*)d_in[0];
    const float* values = (const float*)d_in[1];
    const float* bias   = (const float*)d_in[2];
    const int*   rows   = (const int*)d_in[3];
    const int*   cols   = (const int*)d_in[4];
    float* out = (float*)d_out;

    zero_w_kernel<<<(OUTF * INF / 4) / 256, 256>>>();
    scatter_kernel<<<NNZV / 256, 256>>>(values, rows, cols);
    pack_w_kernel<<<(NM16 * NK16 * 32) / 256, 256>>>();
    pack_x_kernel<<<(int)(((size_t)NN16 * NK16 * 32) / 256), 256>>>(x);

    const int n_tiles_per_split = (NN / 128) / NSPLIT;   // 128
    for (int s = 0; s < NSPLIT; s++) {
        gemm_kernel<<<dim3(OUTF / 128, n_tiles_per_split), 128>>>(
            bias, out, s * n_tiles_per_split);
    }
}

// round 12
// speedup vs baseline: 7.4282x; 1.1497x over previous
#include <cuda_runtime.h>
#include <cuda_fp16.h>
#include <cstdint>

#define OUTF 2048
#define INF  2048
#define NNZV 262144
#define NN   65536

#define NK16 (INF / 16)      // 128 k16 steps
#define NM16 (OUTF / 16)     // 128 m16 tiles
#define NN16 (NN / 16)       // 4096 n16 tiles

#define NSPLIT 4             // gemm split over n (ncu capture targeting)

// ---- device-global scratch ----
__device__ __align__(256) float g_W32[OUTF * INF];                 // 16 MB dense W accumulator
__device__ __align__(256) uint4 g_Wfrag[NM16 * NK16 * 32];         // 8 MB A-fragment-major W
__device__ __align__(256) uint4 g_Xf[(size_t)NN16 * NK16 * 32];    // 256 MB B-fragment-major x

// ---- helpers ----
__device__ __forceinline__ void mma16816(float* c, const uint4& a, uint32_t b0, uint32_t b1) {
    asm volatile(
        "mma.sync.aligned.m16n8k16.row.col.f32.f16.f16.f32 "
        "{%0,%1,%2,%3}, {%4,%5,%6,%7}, {%8,%9}, {%0,%1,%2,%3};"
        : "+f"(c[0]), "+f"(c[1]), "+f"(c[2]), "+f"(c[3])
        : "r"(a.x), "r"(a.y), "r"(a.z), "r"(a.w), "r"(b0), "r"(b1));
}
__device__ __forceinline__ uint32_t packh2(float lo, float hi) {
    __half2 h = __floats2half2_rn(lo, hi);
    return *reinterpret_cast<uint32_t*>(&h);
}

// ---- prologue kernels ----
__global__ void zero_w_kernel() {
    int i = blockIdx.x * blockDim.x + threadIdx.x;
    reinterpret_cast<float4*>(g_W32)[i] = make_float4(0.f, 0.f, 0.f, 0.f);
}
__global__ void scatter_kernel(const float* __restrict__ vals, const int* __restrict__ rows,
                               const int* __restrict__ cols) {
    int i = blockIdx.x * blockDim.x + threadIdx.x;
    atomicAdd(&g_W32[rows[i] * INF + cols[i]], vals[i]);
}
// A-fragment pack (mma.m16n8k16 row-major A): lane l of tile (T=m16, kk) holds
//   x: A[T*16+l/4][kk*16+(l%4)*2 ..+1]   y: same +8 rows
//   z: A[row][k+8..+9]                   w: row+8, k+8
__global__ void pack_w_kernel() {
    int t = blockIdx.x * blockDim.x + threadIdx.x;   // NM16*NK16*32
    int lane = t & 31;
    int kk = (t >> 5) & (NK16 - 1);
    int T = t >> 12;
    int r0 = T * 16 + (lane >> 2);
    int kb = kk * 16 + (lane & 3) * 2;
    const float* W = g_W32;
    uint4 f;
    f.x = packh2(W[r0 * INF + kb],           W[r0 * INF + kb + 1]);
    f.y = packh2(W[(r0 + 8) * INF + kb],     W[(r0 + 8) * INF + kb + 1]);
    f.z = packh2(W[r0 * INF + kb + 8],       W[r0 * INF + kb + 9]);
    f.w = packh2(W[(r0 + 8) * INF + kb + 8], W[(r0 + 8) * INF + kb + 9]);
    g_Wfrag[t] = f;
}
// B-fragment pack (col-major B = x rows as columns): lane l of tile (t=n16, kk):
//   x: {x[n=t*16+l/4][kk*16+(l%4)*2], +1}    y: same col, k+8
//   z: col +8, k lo                          w: col +8, k+8
__global__ void pack_x_kernel(const float* __restrict__ x) {
    size_t t = (size_t)blockIdx.x * blockDim.x + threadIdx.x;   // NN16*NK16*32
    int lane = (int)(t & 31);
    int kk = (int)((t >> 5) & (NK16 - 1));
    int nt = (int)(t >> 12);
    int c0 = nt * 16 + (lane >> 2);
    int kb = kk * 16 + (lane & 3) * 2;
    uint4 f;
    f.x = packh2(x[(size_t)c0 * INF + kb],           x[(size_t)c0 * INF + kb + 1]);
    f.y = packh2(x[(size_t)c0 * INF + kb + 8],       x[(size_t)c0 * INF + kb + 9]);
    f.z = packh2(x[(size_t)(c0 + 8) * INF + kb],     x[(size_t)(c0 + 8) * INF + kb + 1]);
    f.w = packh2(x[(size_t)(c0 + 8) * INF + kb + 8], x[(size_t)(c0 + 8) * INF + kb + 9]);
    g_Xf[t] = f;
}

// ---- GEMM: out[n, o] = sum_k W[o,k] * x[n,k] + bias[o] ----
// Register-only pipeline, fragment-major LDG.128 operands, 3 buffer sets at
// prefetch distance 2. Steady-state loop (kk=0..123 step 3) is BRANCH-FREE:
// all prefetch indices <= kk+4 <= 127, so no guards -> one flat basic block
// per iteration; ptxas can interleave LDG into the mma stream freely.
// Tail: two unguarded consumes for kk=126,127.
__global__ void __launch_bounds__(128, 2)
gemm_kernel(const float* __restrict__ bias, float* __restrict__ out, int n_tile_base) {
    const int lid = threadIdx.x & 31;
    const int wid = threadIdx.x >> 5;
    const int wm = wid & 1;        // 2 m-groups
    const int wn = wid >> 1;       // 2 n-groups
    const int m0 = blockIdx.x * 128;
    const int n0 = (n_tile_base + blockIdx.y) * 128;

    const int m16b = blockIdx.x * 8 + wm * 4;
    const int n16b = (n_tile_base + blockIdx.y) * 8 + wn * 4;

    // Bumped pointers: advance by 32 uint4 per k16 step; tile stride NK16*32.
    const uint4* __restrict__ Ap = g_Wfrag + ((size_t)m16b * NK16) * 32 + lid;
    const uint4* __restrict__ Bp = g_Xf   + ((size_t)n16b * NK16) * 32 + lid;
    const size_t TS = (size_t)NK16 * 32;   // tile stride in uint4

    float acc[4][8][4];
#pragma unroll
    for (int mt = 0; mt < 4; mt++)
#pragma unroll
        for (int nt = 0; nt < 8; nt++)
#pragma unroll
            for (int e = 0; e < 4; e++) acc[mt][nt][e] = 0.f;

    uint4 a0[4], b0[4], a1[4], b1[4], a2[4], b2[4];
#pragma unroll
    for (int i = 0; i < 4; i++) { a0[i] = __ldg(Ap + i * TS);      b0[i] = __ldg(Bp + i * TS); }
#pragma unroll
    for (int i = 0; i < 4; i++) { a1[i] = __ldg(Ap + i * TS + 32); b1[i] = __ldg(Bp + i * TS + 32); }

    auto consume = [&](const uint4* a, const uint4* b) {
#pragma unroll
        for (int mt = 0; mt < 4; mt++)
#pragma unroll
            for (int j = 0; j < 4; j++) {
                mma16816(acc[mt][2 * j],     a[mt], b[j].x, b[j].y);
                mma16816(acc[mt][2 * j + 1], a[mt], b[j].z, b[j].w);
            }
    };

    // steady state: 42 branch-free iterations (consumes kk=0..125, loads to 127)
    const uint4* Ait = Ap;
    const uint4* Bit = Bp;
#pragma unroll 1
    for (int it = 0; it < 42; it++) {
#pragma unroll
        for (int i = 0; i < 4; i++) { a2[i] = __ldg(Ait + i * TS + 64); b2[i] = __ldg(Bit + i * TS + 64); }
        consume(a0, b0);
#pragma unroll
        for (int i = 0; i < 4; i++) { a0[i] = __ldg(Ait + i * TS + 96); b0[i] = __ldg(Bit + i * TS + 96); }
        consume(a1, b1);
#pragma unroll
        for (int i = 0; i < 4; i++) { a1[i] = __ldg(Ait + i * TS + 128); b1[i] = __ldg(Bit + i * TS + 128); }
        consume(a2, b2);
        Ait += 96; Bit += 96;
    }
    // tail: kk = 126, 127 already resident in a0/b0, a1/b1
    consume(a0, b0);
    consume(a1, b1);

    // ---- epilogue: out[n, o] = acc + bias[o] ----
    const int q = lid >> 2;
    const int p2 = (lid & 3) << 1;
#pragma unroll
    for (int mt = 0; mt < 4; mt++) {
        const int o_lo = m0 + wm * 64 + mt * 16 + q;
        const float bv_lo = bias[o_lo];
        const float bv_hi = bias[o_lo + 8];
#pragma unroll
        for (int j = 0; j < 4; j++)
#pragma unroll
            for (int h = 0; h < 2; h++) {
                const int n = n0 + wn * 64 + j * 16 + h * 8 + p2;
                float* o0 = out + (size_t)n * OUTF;
                float* o1 = out + (size_t)(n + 1) * OUTF;
                const float* c = acc[mt][2 * j + h];
                o0[o_lo]     = c[0] + bv_lo;
                o1[o_lo]     = c[1] + bv_lo;
                o0[o_lo + 8] = c[2] + bv_hi;
                o1[o_lo + 8] = c[3] + bv_hi;
            }
    }
}

extern "C" void kernel_launch(void* const* d_in, const int* in_sizes, int n_in,
                              void* d_out, int out_size) {
    (void)in_sizes; (void)n_in; (void)out_size;
    const float* x      = (const float*)d_in[0];
    const float* values = (const float*)d_in[1];
    const float* bias   = (const float*)d_in[2];
    const int*   rows   = (const int*)d_in[3];
    const int*   cols   = (const int*)d_in[4];
    float* out = (float*)d_out;

    zero_w_kernel<<<(OUTF * INF / 4) / 256, 256>>>();
    scatter_kernel<<<NNZV / 256, 256>>>(values, rows, cols);
    pack_w_kernel<<<(NM16 * NK16 * 32) / 256, 256>>>();
    pack_x_kernel<<<(int)(((size_t)NN16 * NK16 * 32) / 256), 256>>>(x);

    const int n_tiles_per_split = (NN / 128) / NSPLIT;   // 128
    for (int s = 0; s < NSPLIT; s++) {
        gemm_kernel<<<dim3(OUTF / 128, n_tiles_per_split), 128>>>(
            bias, out, s * n_tiles_per_split);
    }
}